// round 12
// baseline (speedup 1.0000x reference)
#include <cuda_runtime.h>
#include <cstdint>
#include <math.h>

#define N_ROWS 32768
#define NBITS 64
#define M_BLK 8
#define SUBD 8
#define HID 256
#define NCLS 100

// ---------------- scratch (static __device__; no allocations) ----------------
static __device__ float g_xp[N_ROWS * NBITS];
static __device__ float g_xmap[N_ROWS * NBITS];
static __device__ float g_w[N_ROWS * NCLS];
static __device__ unsigned char g_target[N_ROWS * M_BLK];
static __device__ unsigned long long g_cbits[NCLS];
static __device__ int g_ct[NCLS * M_BLK];
static __device__ int g_tidx[8];      // [0..3] template_map ones, [4..7] template_raw ones
static __device__ unsigned g_keys[4]; // kmap0,kmap1,kraw0,kraw1
static __device__ double g_acc[6];    // 0 mapLoss 1 hits 2 netLoss 3 hamSum 4 maskSum

// ---------------- JAX threefry2x32 (exact) ----------------
__device__ __forceinline__ uint2 threefry(unsigned k0, unsigned k1, unsigned x0, unsigned x1) {
    unsigned k2 = k0 ^ k1 ^ 0x1BD11BDAu;
    x0 += k0; x1 += k1;
#define TF_RND(r) { x0 += x1; x1 = __funnelshift_l(x1, x1, (r)); x1 ^= x0; }
    TF_RND(13) TF_RND(15) TF_RND(26) TF_RND(6)   x0 += k1; x1 += k2 + 1u;
    TF_RND(17) TF_RND(29) TF_RND(16) TF_RND(24)  x0 += k2; x1 += k0 + 2u;
    TF_RND(13) TF_RND(15) TF_RND(26) TF_RND(6)   x0 += k0; x1 += k1 + 3u;
    TF_RND(17) TF_RND(29) TF_RND(16) TF_RND(24)  x0 += k1; x1 += k2 + 4u;
    TF_RND(13) TF_RND(15) TF_RND(26) TF_RND(6)   x0 += k2; x1 += k0 + 5u;
#undef TF_RND
    return make_uint2(x0, x1);
}

// XLA CPU EmitFastTanh (f32): exact constants + FMA Horner + IEEE divide.
__device__ __forceinline__ float xla_tanh(float x) {
    if (fabsf(x) < 0.0004f) return x;
    float xc = fminf(fmaxf(x, -7.90531110763549805f), 7.90531110763549805f);
    float x2 = xc * xc;
    float p = -2.76076847742355e-16f;
    p = __fmaf_rn(p, x2, 2.00018790482477e-13f);
    p = __fmaf_rn(p, x2, -8.60467152213735e-11f);
    p = __fmaf_rn(p, x2, 5.12229709037114e-08f);
    p = __fmaf_rn(p, x2, 1.48572235717979e-05f);
    p = __fmaf_rn(p, x2, 6.37261928875436e-04f);
    p = __fmaf_rn(p, x2, 4.89352455891786e-03f);
    p = p * xc;
    float q = 1.19825839466702e-06f;
    q = __fmaf_rn(q, x2, 1.18534705686654e-04f);
    q = __fmaf_rn(q, x2, 2.26843463243900e-03f);
    q = __fmaf_rn(q, x2, 4.89352518554385e-03f);
    return __fdiv_rn(p, q);
}
// XLA logistic expansion: 0.5 + 0.5*tanh(0.5*x); silu = x * logistic(x)
__device__ __forceinline__ float xla_silu(float a) {
    float s = __fmaf_rn(0.5f, xla_tanh(0.5f * a), 0.5f);
    return a * s;
}

// Template decode robust to bool(u8) vs int32/float32 serialization.
__device__ void decode_template(const void* p, int* out4) {
    const unsigned* w = (const unsigned*)p;
    int cnt = 0; bool ok = true; int idx[4];
    for (int j = 0; j < NBITS; j++) {
        unsigned v = w[j];
        if (v == 0u) continue;
        if (v == 1u || v == 0x3f800000u) { if (cnt < 4) idx[cnt] = j; cnt++; }
        else { ok = false; break; }
    }
    if (ok && cnt == 4) { for (int e = 0; e < 4; e++) out4[e] = idx[e]; return; }
    const unsigned char* b = (const unsigned char*)p;
    cnt = 0;
    for (int j = 0; j < NBITS; j++) if (b[j]) { if (cnt < 4) out4[cnt] = j; cnt++; }
}

// ---------------- prep: zero accum, keys (PARTITIONABLE fold-like split), templates, centroid bits ----------------
__global__ void prep_kernel(const float* __restrict__ centroids, const int* __restrict__ perm,
                            const void* tmap, const void* traw) {
    int t = threadIdx.x;
    if (t == 0) {
        for (int i = 0; i < 6; i++) g_acc[i] = 0.0;
        // jax_threefry_partitionable: split(key(1)) = [TF(0,1,(0,0)), TF(0,1,(0,1))], each key = both lanes
        uint2 a = threefry(0u, 1u, 0u, 0u);
        uint2 b = threefry(0u, 1u, 0u, 1u);
        g_keys[0] = a.x; g_keys[1] = a.y; // kmap
        g_keys[2] = b.x; g_keys[3] = b.y; // kraw
        decode_template(tmap, &g_tidx[0]);
        decode_template(traw, &g_tidx[4]);
    }
    if (t < NCLS) {
        unsigned long long u = 0ull;
        for (int j = 0; j < NBITS; j++)
            if (centroids[t * NBITS + perm[j]] > 0.f) u |= (1ull << j);
        g_cbits[t] = u;
        for (int m = 0; m < M_BLK; m++)
            g_ct[t * M_BLK + m] = (int)((u >> (8 * m)) & 0xFFull);
    }
}

// ---------------- per-row: permute, bit-flips, targets, hamming, weights ----------------
__global__ void __launch_bounds__(256) row_kernel(const float* __restrict__ x,
                                                  const int* __restrict__ y,
                                                  const int* __restrict__ perm) {
    __shared__ int sperm[NBITS];
    __shared__ unsigned kw[8][NBITS];
    __shared__ unsigned long long scb[NCLS];
    __shared__ double sham[8], smsk[8];
    int t = threadIdx.x, wid = t >> 5, lane = t & 31;
    if (t < NBITS) sperm[t] = perm[t];
    if (t < NCLS) scb[t] = g_cbits[t];
    __syncthreads();

    int n = blockIdx.x * 8 + wid;
    int j0 = lane, j1 = lane + 32;
    float xp0 = x[n * NBITS + sperm[j0]];
    float xp1 = x[n * NBITS + sperm[j1]];
    g_xp[n * NBITS + j0] = xp0;
    g_xp[n * NBITS + j1] = xp1;

    unsigned e0 = (unsigned)n * NBITS + (unsigned)j0;
    unsigned e1 = (unsigned)n * NBITS + (unsigned)j1;

    unsigned long long flips[2];
#pragma unroll
    for (int q = 0; q < 2; q++) {
        unsigned k0 = g_keys[q * 2], k1 = g_keys[q * 2 + 1];
        // partitionable random_bits: counter = (hi=0, lo=flat_index); bits = lane0 ^ lane1
        uint2 r0 = threefry(k0, k1, 0u, e0);
        uint2 r1 = threefry(k0, k1, 0u, e1);
        unsigned kb0 = (r0.x ^ r0.y) >> 9; // uniform float order == (bits>>9, idx)
        unsigned kb1 = (r1.x ^ r1.y) >> 9;
        kw[wid][j0] = kb0; kw[wid][j1] = kb1;
        __syncwarp();
        unsigned long long f = 0ull;
#pragma unroll
        for (int e = 0; e < 4; e++) {
            int ti = g_tidx[q * 4 + e];
            unsigned kt = kw[wid][ti];
            unsigned b0 = __ballot_sync(0xFFFFFFFFu, (kb0 < kt) || (kb0 == kt && j0 < ti));
            unsigned b1 = __ballot_sync(0xFFFFFFFFu, (kb1 < kt) || (kb1 == kt && j1 < ti));
            f |= (1ull << (__popc(b0) + __popc(b1))); // stable-argsort rank of rand[ti]
        }
        flips[q] = f;
        __syncwarp();
    }
    // map-net input (template_map flips)
    g_xmap[n * NBITS + j0] = ((flips[0] >> j0) & 1ull) ? -xp0 : xp0;
    g_xmap[n * NBITS + j1] = ((flips[0] >> j1) & 1ull) ? -xp1 : xp1;
    // raw-flip target bytes
    {
        bool bit0 = ((flips[1] >> j0) & 1ull) ? (xp0 < 0.f) : (xp0 > 0.f);
        bool bit1 = ((flips[1] >> j1) & 1ull) ? (xp1 < 0.f) : (xp1 > 0.f);
        unsigned br0 = __ballot_sync(0xFFFFFFFFu, bit0);
        unsigned br1 = __ballot_sync(0xFFFFFFFFu, bit1);
        if (lane < M_BLK) {
            unsigned wsel = (lane < 4) ? br0 : br1;
            g_target[n * M_BLK + lane] = (unsigned char)((wsel >> ((lane & 3) * 8)) & 0xFFu);
        }
    }
    // hamming stats + class weights
    unsigned bx0 = __ballot_sync(0xFFFFFFFFu, xp0 > 0.f);
    unsigned bx1 = __ballot_sync(0xFFFFFFFFu, xp1 > 0.f);
    unsigned long long xb = (unsigned long long)bx0 | ((unsigned long long)bx1 << 32);
    int xpop = __popc(bx0) + __popc(bx1);
    int msk[4]; int cnt = 0;
#pragma unroll
    for (int k = 0; k < 4; k++) {
        int c = lane + 32 * k;
        msk[k] = (c < NCLS) ? (y[n * NCLS + c] > 0) : 0;
        cnt += msk[k];
    }
    cnt = __reduce_add_sync(0xFFFFFFFFu, cnt);
    float winv = 1.0f / (float)cnt;
    double hamp = 0.0;
#pragma unroll
    for (int k = 0; k < 4; k++) {
        int c = lane + 32 * k;
        if (c < NCLS) {
            g_w[n * NCLS + c] = msk[k] ? winv : 0.f;
            if (msk[k])
                hamp += (double)(xpop + __popcll(scb[c]) - 2 * __popcll(xb & scb[c]));
        }
    }
    for (int off = 16; off; off >>= 1) hamp += __shfl_down_sync(0xFFFFFFFFu, hamp, off);
    if (lane == 0) { sham[wid] = hamp; smsk[wid] = (double)cnt; }
    __syncthreads();
    if (t == 0) {
        double h = 0, mm = 0;
        for (int w2 = 0; w2 < 8; w2++) { h += sham[w2]; mm += smsk[w2]; }
        atomicAdd(&g_acc[3], h);
        atomicAdd(&g_acc[4], mm);
    }
}

// ---------------- fused MLP (layer1 + XLA-silu + layer2) + loss epilogue ----------------
// CTA: 256 threads = 8 warps, 64 rows, one m-group. K-tiled (16) layer-2, serial ascending-k FFMA.
template <bool IS_MAP>
__global__ void __launch_bounds__(256, 2) net_kernel(const float* __restrict__ W1,
                                                     const float* __restrict__ b1,
                                                     const float* __restrict__ W2,
                                                     const float* __restrict__ b2) {
    __shared__ float W1s[SUBD * HID];
    __shared__ float b1s[HID];
    __shared__ float b2s[HID];
    __shared__ float Xs[64 * SUBD];
    __shared__ alignas(16) float Ws[16 * HID];
    __shared__ alignas(16) float Hs[64 * 16];
    __shared__ float rowbuf[8][HID];
    __shared__ int ctm[NCLS];
    __shared__ double sA[8], sB[8];

    const float* X = IS_MAP ? g_xmap : g_xp;
    int t = threadIdx.x, tx = t & 31, ty = t >> 5;
    int mi = blockIdx.x & 7, tile = blockIdx.x >> 3;
    int row0 = tile * 64;

    for (int i = t; i < SUBD * HID; i += 256) W1s[i] = W1[mi * SUBD * HID + i];
    b1s[t] = b1[mi * HID + t];
    b2s[t] = b2[mi * HID + t];
    for (int i = t; i < 64 * SUBD; i += 256) {
        int r = i >> 3, s = i & 7;
        Xs[i] = X[(row0 + r) * NBITS + mi * SUBD + s];
    }
    if (!IS_MAP && t < NCLS) ctm[t] = g_ct[t * M_BLK + mi];

    float acc[8][8];
#pragma unroll
    for (int rr = 0; rr < 8; rr++)
#pragma unroll
        for (int oc = 0; oc < 8; oc++) acc[rr][oc] = 0.f;
    __syncthreads();

    const float* W2m = W2 + mi * HID * HID;
    for (int kt = 0; kt < 16; kt++) {
        // stage W2 k-tile (16 x 256) via float4
#pragma unroll
        for (int q = 0; q < 4; q++) {
            int f4 = t + 256 * q;
            int k = f4 >> 6, o4 = f4 & 63;
            ((float4*)Ws)[k * 64 + o4] = ((const float4*)(W2m + (kt * 16 + k) * HID))[o4];
        }
        // fused layer-1 for this k-tile: dot (ascending i, FMA from 0), bias AFTER, XLA silu
        {
            int k = t & 15, r0 = t >> 4;
            int kg = kt * 16 + k;
            float w1r[SUBD];
#pragma unroll
            for (int s = 0; s < SUBD; s++) w1r[s] = W1s[s * HID + kg];
            float bb = b1s[kg];
#pragma unroll
            for (int q = 0; q < 4; q++) {
                int r = r0 + 16 * q;
                float a = 0.f;
#pragma unroll
                for (int s = 0; s < SUBD; s++) a = __fmaf_rn(Xs[r * SUBD + s], w1r[s], a);
                a = a + bb;
                Hs[r * 16 + k] = xla_silu(a);
            }
        }
        __syncthreads();
#pragma unroll
        for (int k4 = 0; k4 < 4; k4++) {
            float4 hq[8];
#pragma unroll
            for (int rr = 0; rr < 8; rr++)
                hq[rr] = ((float4*)Hs)[(ty * 8 + rr) * 4 + k4];
#pragma unroll
            for (int kk = 0; kk < 4; kk++) {
                float wv[8];
#pragma unroll
                for (int oc = 0; oc < 8; oc++)
                    wv[oc] = Ws[(k4 * 4 + kk) * HID + tx + 32 * oc];
#pragma unroll
                for (int rr = 0; rr < 8; rr++) {
                    float h = (kk == 0) ? hq[rr].x : (kk == 1) ? hq[rr].y
                              : (kk == 2) ? hq[rr].z : hq[rr].w;
#pragma unroll
                    for (int oc = 0; oc < 8; oc++)
                        acc[rr][oc] = __fmaf_rn(h, wv[oc], acc[rr][oc]);
                }
            }
        }
        __syncthreads();
    }
#pragma unroll
    for (int rr = 0; rr < 8; rr++)
#pragma unroll
        for (int oc = 0; oc < 8; oc++) acc[rr][oc] += b2s[tx + 32 * oc];

    // epilogue: warp ty owns rows row0 + ty*8 .. +7; full 256 logits live in-warp
    double accA = 0.0, accB = 0.0;
    for (int rr = 0; rr < 8; rr++) {
        int rg = row0 + ty * 8 + rr;
#pragma unroll
        for (int oc = 0; oc < 8; oc++) rowbuf[ty][tx + 32 * oc] = acc[rr][oc];
        __syncwarp();
        float mv = -1e30f; int mix = 0;
#pragma unroll
        for (int oc = 0; oc < 8; oc++) {
            float v = acc[rr][oc];
            if (v > mv) { mv = v; mix = tx + 32 * oc; }
        }
        for (int off = 16; off; off >>= 1) {
            float om = __shfl_down_sync(0xFFFFFFFFu, mv, off);
            int oi = __shfl_down_sync(0xFFFFFFFFu, mix, off);
            if (om > mv || (om == mv && oi < mix)) { mv = om; mix = oi; }
        }
        mv = __shfl_sync(0xFFFFFFFFu, mv, 0);
        mix = __shfl_sync(0xFFFFFFFFu, mix, 0);
        float se = 0.f;
#pragma unroll
        for (int oc = 0; oc < 8; oc++) se += __expf(acc[rr][oc] - mv);
        for (int off = 16; off; off >>= 1) se += __shfl_xor_sync(0xFFFFFFFFu, se, off);
        float lse = logf(se) + mv;
        if (IS_MAP) {
            if (tx == 0) {
                int tgt = (int)g_target[rg * M_BLK + mi];
                float picked = rowbuf[ty][tgt];
                accA += (double)(lse - picked);
                accB += (mix == tgt) ? 1.0 : 0.0;
            }
        } else {
            float part = 0.f;
            for (int c = tx; c < NCLS; c += 32)
                part += g_w[rg * NCLS + c] * rowbuf[ty][ctm[c]];
            for (int off = 16; off; off >>= 1) part += __shfl_xor_sync(0xFFFFFFFFu, part, off);
            if (tx == 0) accA += (double)(lse - part);
        }
        __syncwarp();
    }
    if (tx == 0) { sA[ty] = accA; sB[ty] = accB; }
    __syncthreads();
    if (t == 0) {
        double a = 0, b = 0;
        for (int w2 = 0; w2 < 8; w2++) { a += sA[w2]; b += sB[w2]; }
        if (IS_MAP) { atomicAdd(&g_acc[0], a); atomicAdd(&g_acc[1], b); }
        else atomicAdd(&g_acc[2], a);
    }
}

__global__ void finalize_kernel(float* out) {
    if (threadIdx.x == 0) {
        double inv = 1.0 / (double)N_ROWS;
        double mapLoss = g_acc[0] * inv;
        double hit = g_acc[1] / ((double)N_ROWS * (double)M_BLK);
        double netLoss = g_acc[2] * inv;
        double ham = g_acc[3] / g_acc[4];
        out[0] = (float)(netLoss + mapLoss);
        out[1] = (float)netLoss;
        out[2] = (float)mapLoss;
        out[3] = (float)hit;
        out[4] = (float)ham;
    }
}

extern "C" void kernel_launch(void* const* d_in, const int* in_sizes, int n_in,
                              void* d_out, int out_size) {
    const float* x    = (const float*)d_in[0];
    const int*   y    = (const int*)d_in[1];
    const float* cent = (const float*)d_in[2];
    const int*   perm = (const int*)d_in[3];
    const void*  tmap = d_in[4];
    const void*  traw = d_in[5];
    const float* W1   = (const float*)d_in[6];
    const float* b1   = (const float*)d_in[7];
    const float* W2   = (const float*)d_in[8];
    const float* b2   = (const float*)d_in[9];

    prep_kernel<<<1, 128>>>(cent, perm, tmap, traw);
    row_kernel<<<N_ROWS / 8, 256>>>(x, y, perm);
    net_kernel<true><<<(N_ROWS / 64) * 8, 256>>>(W1, b1, W2, b2);
    net_kernel<false><<<(N_ROWS / 64) * 8, 256>>>(W1, b1, W2, b2);
    finalize_kernel<<<1, 32>>>((float*)d_out);
}